// round 11
// baseline (speedup 1.0000x reference)
#include <cuda_runtime.h>
#include <cuda_bf16.h>
#include <cuda_fp16.h>
#include <cstdint>

// Problem constants
#define B_SZ 4
#define N_SEQ 2048
#define D_MODEL 1024
#define N_HEADS 16
#define HEAD_DIM 64
#define BH (B_SZ * N_HEADS)          // 64
#define TOKENS (B_SZ * N_SEQ)        // 8192
#define QKV_COLS (3 * D_MODEL)       // 3072

typedef __nv_bfloat16 bf16;

// ---------------------------------------------------------------------------
// Scratch (module-static device memory; no runtime allocation)
// ---------------------------------------------------------------------------
#define QKV_ELEMS ((size_t)BH * N_SEQ * HEAD_DIM)   // 8388608
__device__ bf16 g_x_hi[(size_t)TOKENS * D_MODEL];
__device__ bf16 g_x_lo[(size_t)TOKENS * D_MODEL];
__device__ bf16 g_wqkv_hi[(size_t)QKV_COLS * D_MODEL];   // [n][k]
__device__ bf16 g_wqkv_lo[(size_t)QKV_COLS * D_MODEL];
__device__ bf16 g_wout_hi[(size_t)D_MODEL * D_MODEL];    // [n][k]
__device__ bf16 g_wout_lo[(size_t)D_MODEL * D_MODEL];
__device__ __half g_q_f[QKV_ELEMS];   // [bh][n][dh], pre-scaled by 0.125 (fp16)
__device__ __half g_k_f[QKV_ELEMS];   // [bh][n][dh]                     (fp16)
__device__ __half g_vt_f[QKV_ELEMS];  // [bh][dh][n]  (transposed)        (fp16)
__device__ bf16 g_att_hi[(size_t)TOKENS * D_MODEL];  // [token][h*64+dh]
__device__ bf16 g_att_lo[(size_t)TOKENS * D_MODEL];

// ---------------------------------------------------------------------------
// Helpers
// ---------------------------------------------------------------------------
__device__ __forceinline__ uint32_t smem_u32(const void* p) {
    uint32_t a;
    asm("{ .reg .u64 t; cvta.to.shared.u64 t, %1; cvt.u32.u64 %0, t; }"
        : "=r"(a) : "l"(p));
    return a;
}

__device__ __forceinline__ void split1(float x, unsigned short& h, unsigned short& l) {
    bf16 bh_ = __float2bfloat16(x);
    float r = x - __bfloat162float(bh_);
    bf16 bl_ = __float2bfloat16(r);
    h = __bfloat16_as_ushort(bh_);
    l = __bfloat16_as_ushort(bl_);
}

__device__ __forceinline__ void split_pack2(float x, float y, uint32_t& hi, uint32_t& lo) {
    unsigned short hx, lx, hy, ly;
    split1(x, hx, lx);
    split1(y, hy, ly);
    hi = (uint32_t)hx | ((uint32_t)hy << 16);
    lo = (uint32_t)lx | ((uint32_t)ly << 16);
}

__device__ __forceinline__ uint32_t pack_h2(float x, float y) {
    __half2 h = __floats2half2_rn(x, y);
    return *(uint32_t*)&h;
}

#define LDSM_X4(r0, r1, r2, r3, addr) \
    asm volatile("ldmatrix.sync.aligned.m8n8.x4.shared.b16 {%0,%1,%2,%3}, [%4];" \
                 : "=r"(r0), "=r"(r1), "=r"(r2), "=r"(r3) : "r"(addr))

#define MMA_BF16(c, a, b0, b1) \
    asm volatile("mma.sync.aligned.m16n8k16.row.col.f32.bf16.bf16.f32 " \
                 "{%0,%1,%2,%3}, {%4,%5,%6,%7}, {%8,%9}, {%0,%1,%2,%3};" \
                 : "+f"((c)[0]), "+f"((c)[1]), "+f"((c)[2]), "+f"((c)[3]) \
                 : "r"((a)[0]), "r"((a)[1]), "r"((a)[2]), "r"((a)[3]), \
                   "r"(b0), "r"(b1))

#define MMA_F16(c, a, b0, b1) \
    asm volatile("mma.sync.aligned.m16n8k16.row.col.f32.f16.f16.f32 " \
                 "{%0,%1,%2,%3}, {%4,%5,%6,%7}, {%8,%9}, {%0,%1,%2,%3};" \
                 : "+f"((c)[0]), "+f"((c)[1]), "+f"((c)[2]), "+f"((c)[3]) \
                 : "r"((a)[0]), "r"((a)[1]), "r"((a)[2]), "r"((a)[3]), \
                   "r"(b0), "r"(b1))

#define CP16(saddr, gptr) \
    asm volatile("cp.async.cg.shared.global [%0], [%1], 16;" \
                 :: "r"(saddr), "l"(gptr) : "memory")
#define CP_COMMIT() asm volatile("cp.async.commit_group;" ::: "memory")
#define CP_WAIT(n)  asm volatile("cp.async.wait_group %0;" :: "n"(n) : "memory")

// ---------------------------------------------------------------------------
// Conversion kernels
// ---------------------------------------------------------------------------
__global__ void split_x_kernel(const float* __restrict__ x, bf16* __restrict__ hi,
                               bf16* __restrict__ lo, int n4)
{
    int idx = blockIdx.x * 256 + threadIdx.x;
    if (idx >= n4) return;
    float4 v = ((const float4*)x)[idx];
    uint32_t h0, l0, h1, l1;
    split_pack2(v.x, v.y, h0, l0);
    split_pack2(v.z, v.w, h1, l1);
    ((uint2*)hi)[idx] = make_uint2(h0, h1);
    ((uint2*)lo)[idx] = make_uint2(l0, l1);
}

__global__ void split_wt_kernel(const float* __restrict__ W, bf16* __restrict__ hi,
                                bf16* __restrict__ lo, int N, int K)
{
    __shared__ float t[32][33];
    const int tx = threadIdx.x, ty = threadIdx.y;  // block (32,8)
    const int n0 = blockIdx.x * 32, k0 = blockIdx.y * 32;
#pragma unroll
    for (int s = 0; s < 4; s++)
        t[ty + 8 * s][tx] = W[(size_t)(k0 + ty + 8 * s) * N + n0 + tx];
    __syncthreads();
#pragma unroll
    for (int s = 0; s < 4; s++) {
        const int nn = ty + 8 * s, kk = tx;
        float v = t[kk][nn];
        unsigned short h, l;
        split1(v, h, l);
        hi[(size_t)(n0 + nn) * K + k0 + kk] = __ushort_as_bfloat16(h);
        lo[(size_t)(n0 + nn) * K + k0 + kk] = __ushort_as_bfloat16(l);
    }
}

// ---------------------------------------------------------------------------
// Warp-MMA split-bf16 GEMM, cp.async double-buffered.
// mode 0: QKV epilogue -> fp16 Q/K/Vt; mode 1: fp32 write + bias.
// ---------------------------------------------------------------------------
#define SSTRIDE 40
#define G_ARR_B (128 * SSTRIDE * 2)          // 10240 bytes per array
#define G_STAGE_B (4 * G_ARR_B)              // 40960 bytes per stage
#define G_SMEM_B (2 * G_STAGE_B)             // 81920

__global__ void __launch_bounds__(256, 2)
mma_gemm_kernel(const bf16* __restrict__ Ah_g, const bf16* __restrict__ Al_g,
                const bf16* __restrict__ Bh_g, const bf16* __restrict__ Bl_g,
                const float* __restrict__ bias, float* __restrict__ C,
                int M, int N, int K, int mode)
{
    extern __shared__ __align__(16) char dsm[];
    const uint32_t sb0 = smem_u32(dsm);

    const int tid  = threadIdx.x;
    const int wid  = tid >> 5;
    const int lane = tid & 31;
    const int wr   = wid >> 1;
    const int wc   = wid & 1;

    const int row0 = blockIdx.y * 128;
    const int col0 = blockIdx.x * 128;

    float acc[2][8][4];
#pragma unroll
    for (int i = 0; i < 2; i++)
#pragma unroll
        for (int j = 0; j < 8; j++)
#pragma unroll
            for (int c = 0; c < 4; c++) acc[i][j][c] = 0.f;

    const uint32_t a_row = lane & 15;
    const uint32_t a_kof = (lane >> 4) << 3;
    const uint32_t b_nof = ((lane >> 4) << 3) + (lane & 7);
    const uint32_t b_kof = ((lane >> 3) & 1) << 3;

    const int f0 = tid, f1 = 256 + tid;
    const int r_0 = f0 >> 2, c8_0 = (f0 & 3) << 3;
    const int r_1 = f1 >> 2, c8_1 = (f1 & 3) << 3;
    const uint32_t so_0 = ((uint32_t)r_0 * SSTRIDE + c8_0) * 2;
    const uint32_t so_1 = ((uint32_t)r_1 * SSTRIDE + c8_1) * 2;

#define G_ISSUE(stage, k0_)                                                     \
    do {                                                                        \
        uint32_t sb = sb0 + (stage) * G_STAGE_B;                                \
        size_t ga0 = (size_t)(row0 + r_0) * K + (k0_) + c8_0;                   \
        size_t ga1 = (size_t)(row0 + r_1) * K + (k0_) + c8_1;                   \
        size_t gb0 = (size_t)(col0 + r_0) * K + (k0_) + c8_0;                   \
        size_t gb1 = (size_t)(col0 + r_1) * K + (k0_) + c8_1;                   \
        CP16(sb + 0 * G_ARR_B + so_0, Ah_g + ga0);                              \
        CP16(sb + 0 * G_ARR_B + so_1, Ah_g + ga1);                              \
        CP16(sb + 1 * G_ARR_B + so_0, Al_g + ga0);                              \
        CP16(sb + 1 * G_ARR_B + so_1, Al_g + ga1);                              \
        CP16(sb + 2 * G_ARR_B + so_0, Bh_g + gb0);                              \
        CP16(sb + 2 * G_ARR_B + so_1, Bh_g + gb1);                              \
        CP16(sb + 3 * G_ARR_B + so_0, Bl_g + gb0);                              \
        CP16(sb + 3 * G_ARR_B + so_1, Bl_g + gb1);                              \
        CP_COMMIT();                                                            \
    } while (0)

    const int niter = K / 32;
    G_ISSUE(0, 0);

    for (int it = 0; it < niter; it++) {
        if (it + 1 < niter) {
            G_ISSUE((it + 1) & 1, (it + 1) * 32);
            CP_WAIT(1);
        } else {
            CP_WAIT(0);
        }
        __syncthreads();

        const uint32_t sb = sb0 + (it & 1) * G_STAGE_B;
        const uint32_t ah_b = sb + 0 * G_ARR_B;
        const uint32_t al_b = sb + 1 * G_ARR_B;
        const uint32_t bh_b = sb + 2 * G_ARR_B;
        const uint32_t bl_b = sb + 3 * G_ARR_B;

#pragma unroll
        for (int ks = 0; ks < 2; ks++) {
            const uint32_t kk = ks * 16;
            uint32_t ahr[2][4], alr[2][4];
#pragma unroll
            for (int i = 0; i < 2; i++) {
                uint32_t eoff = ((wr * 32 + i * 16 + a_row) * SSTRIDE + kk + a_kof) * 2;
                LDSM_X4(ahr[i][0], ahr[i][1], ahr[i][2], ahr[i][3], ah_b + eoff);
                LDSM_X4(alr[i][0], alr[i][1], alr[i][2], alr[i][3], al_b + eoff);
            }
#pragma unroll
            for (int jp = 0; jp < 4; jp++) {
                const uint32_t nb = wc * 64 + jp * 16;
                uint32_t eoff = ((nb + b_nof) * SSTRIDE + kk + b_kof) * 2;
                uint32_t bhr[4], blr[4];
                LDSM_X4(bhr[0], bhr[1], bhr[2], bhr[3], bh_b + eoff);
                LDSM_X4(blr[0], blr[1], blr[2], blr[3], bl_b + eoff);
#pragma unroll
                for (int i = 0; i < 2; i++) {
                    MMA_BF16(acc[i][2 * jp + 0], ahr[i], bhr[0], bhr[1]);
                    MMA_BF16(acc[i][2 * jp + 1], ahr[i], bhr[2], bhr[3]);
                    MMA_BF16(acc[i][2 * jp + 0], ahr[i], blr[0], blr[1]);
                    MMA_BF16(acc[i][2 * jp + 1], ahr[i], blr[2], blr[3]);
                    MMA_BF16(acc[i][2 * jp + 0], alr[i], bhr[0], bhr[1]);
                    MMA_BF16(acc[i][2 * jp + 1], alr[i], bhr[2], bhr[3]);
                }
            }
        }
        __syncthreads();
    }
#undef G_ISSUE

    const int mbase = row0 + wr * 32 + (lane >> 2);
    const int nbase = col0 + wc * 64 + ((lane & 3) << 1);

    if (mode == 0) {
#pragma unroll
        for (int i = 0; i < 2; i++) {
#pragma unroll
            for (int rr = 0; rr < 2; rr++) {
                const int m  = mbase + i * 16 + rr * 8;
                const int bb = m >> 11;
                const int nn = m & 2047;
#pragma unroll
                for (int j = 0; j < 8; j++) {
                    const int jg0 = nbase + j * 8;
                    const int sel = jg0 >> 10;
                    const int hh  = (jg0 >> 6) & 15;
                    const int dh  = jg0 & 63;
                    const int bhd = bb * N_HEADS + hh;
                    float v0 = acc[i][j][rr * 2 + 0] + bias[jg0];
                    float v1 = acc[i][j][rr * 2 + 1] + bias[jg0 + 1];
                    if (sel == 0) { v0 *= 0.125f; v1 *= 0.125f; }
                    if (sel == 0) {
                        size_t o = ((size_t)bhd * N_SEQ + nn) * HEAD_DIM + dh;
                        *(uint32_t*)&g_q_f[o] = pack_h2(v0, v1);
                    } else if (sel == 1) {
                        size_t o = ((size_t)bhd * N_SEQ + nn) * HEAD_DIM + dh;
                        *(uint32_t*)&g_k_f[o] = pack_h2(v0, v1);
                    } else {
                        size_t o = ((size_t)bhd * HEAD_DIM + dh) * N_SEQ + nn;
                        g_vt_f[o] = __float2half_rn(v0);
                        g_vt_f[o + N_SEQ] = __float2half_rn(v1);
                    }
                }
            }
        }
    } else {
#pragma unroll
        for (int i = 0; i < 2; i++) {
#pragma unroll
            for (int rr = 0; rr < 2; rr++) {
                const int m = mbase + i * 16 + rr * 8;
                float* cp = C + (size_t)m * N;
#pragma unroll
                for (int j = 0; j < 8; j++) {
#pragma unroll
                    for (int c = 0; c < 2; c++) {
                        const int jg = nbase + j * 8 + c;
                        cp[jg] = acc[i][j][rr * 2 + c] + bias[jg];
                    }
                }
            }
        }
    }
}

// ---------------------------------------------------------------------------
// mma.sync fp16 flash attention, cp.async double-buffered K/V, 2 CTAs/SM.
// CTA: (head bh, 128-query tile). 8 warps x m16. Single fp16 operands,
// fp32 accumulation. S: 32 MMAs/iter, PV: 32 MMAs/iter (3x fewer than split).
// smem: Q [128][72] fp16 + 2 stages x (K|V) [64][72] fp16 = 55296 B.
// ---------------------------------------------------------------------------
#define AQ_STR 72
#define A_Q_ARR_B (128 * AQ_STR * 2)     // 18432
#define A_KV_ARR_B (64 * AQ_STR * 2)     // 9216
#define A_KV_STAGE_B (2 * A_KV_ARR_B)    // 18432
#define A_KV_BASE A_Q_ARR_B              // 18432
#define ATT_SMEM_BYTES (A_KV_BASE + 2 * A_KV_STAGE_B)   // 55296

__global__ void __launch_bounds__(256, 2)
attn_mma_kernel()
{
    extern __shared__ __align__(16) char dsm[];
    const uint32_t sb0  = smem_u32(dsm);
    const uint32_t q_b  = sb0;

    const int tid  = threadIdx.x;
    const int w    = tid >> 5;
    const int lane = tid & 31;
    const int bh   = blockIdx.y;
    const int qt   = blockIdx.x;

    const __half* ksrc = g_k_f + (size_t)bh * N_SEQ * HEAD_DIM;
    const __half* vsrc = g_vt_f + (size_t)bh * HEAD_DIM * N_SEQ;

    const int f0 = tid, f1 = 256 + tid;
    const int kr0 = f0 >> 3, kc0 = (f0 & 7) << 3;
    const int kr1 = f1 >> 3, kc1 = (f1 & 7) << 3;
    const uint32_t kso0 = ((uint32_t)kr0 * AQ_STR + kc0) * 2;
    const uint32_t kso1 = ((uint32_t)kr1 * AQ_STR + kc1) * 2;

#define A_ISSUE(stage, kt_)                                                     \
    do {                                                                        \
        uint32_t sb = sb0 + A_KV_BASE + (stage) * A_KV_STAGE_B;                 \
        size_t gk0 = (size_t)((kt_) * 64 + kr0) * HEAD_DIM + kc0;               \
        size_t gk1 = (size_t)((kt_) * 64 + kr1) * HEAD_DIM + kc1;               \
        size_t gv0 = (size_t)kr0 * N_SEQ + (kt_) * 64 + kc0;                    \
        size_t gv1 = (size_t)kr1 * N_SEQ + (kt_) * 64 + kc1;                    \
        CP16(sb + 0 * A_KV_ARR_B + kso0, ksrc + gk0);                           \
        CP16(sb + 0 * A_KV_ARR_B + kso1, ksrc + gk1);                           \
        CP16(sb + 1 * A_KV_ARR_B + kso0, vsrc + gv0);                           \
        CP16(sb + 1 * A_KV_ARR_B + kso1, vsrc + gv1);                           \
        CP_COMMIT();                                                            \
    } while (0)

    A_ISSUE(0, 0);

    // Load Q tile [128][64] fp16 (plain loads, once)
    const __half* qsrc = g_q_f + ((size_t)bh * N_SEQ + qt * 128) * HEAD_DIM;
#pragma unroll
    for (int i = 0; i < 4; i++) {
        int f  = i * 256 + tid;
        int r  = f >> 3;
        int c8 = (f & 7) << 3;
        uint32_t so = ((uint32_t)r * AQ_STR + c8) * 2;
        *(uint4*)(dsm + so) = *(const uint4*)(qsrc + r * HEAD_DIM + c8);
    }
    __syncthreads();

    const uint32_t a_row = lane & 15;
    const uint32_t a_kof = (lane >> 4) << 3;
    const uint32_t b_nof = ((lane >> 4) << 3) + (lane & 7);
    const uint32_t b_kof = ((lane >> 3) & 1) << 3;

    float m0 = -1e30f, m1 = -1e30f, l0 = 0.f, l1 = 0.f;
    float o[8][4];
#pragma unroll
    for (int j = 0; j < 8; j++)
#pragma unroll
        for (int c = 0; c < 4; c++) o[j][c] = 0.f;

    const int nkt = N_SEQ / 64;
    for (int kt = 0; kt < nkt; kt++) {
        if (kt + 1 < nkt) {
            A_ISSUE((kt + 1) & 1, kt + 1);
            CP_WAIT(1);
        } else {
            CP_WAIT(0);
        }
        __syncthreads();

        const uint32_t sb  = sb0 + A_KV_BASE + (kt & 1) * A_KV_STAGE_B;
        const uint32_t k_b = sb;
        const uint32_t v_b = sb + A_KV_ARR_B;

        // S = Q @ K^T (scale pre-folded into Q)
        float s[8][4];
#pragma unroll
        for (int j = 0; j < 8; j++)
#pragma unroll
            for (int c = 0; c < 4; c++) s[j][c] = 0.f;

#pragma unroll
        for (int t = 0; t < 4; t++) {
            uint32_t q4[4];
            {
                uint32_t eoff = ((w * 16 + a_row) * AQ_STR + t * 16 + a_kof) * 2;
                LDSM_X4(q4[0], q4[1], q4[2], q4[3], q_b + eoff);
            }
#pragma unroll
            for (int g = 0; g < 4; g++) {
                uint32_t eoff = ((g * 16 + b_nof) * AQ_STR + t * 16 + b_kof) * 2;
                uint32_t k4[4];
                LDSM_X4(k4[0], k4[1], k4[2], k4[3], k_b + eoff);
                MMA_F16(s[2 * g + 0], q4, k4[0], k4[1]);
                MMA_F16(s[2 * g + 1], q4, k4[2], k4[3]);
            }
        }

        // Online softmax
        float mx0 = -1e30f, mx1 = -1e30f;
#pragma unroll
        for (int j = 0; j < 8; j++) {
            mx0 = fmaxf(mx0, fmaxf(s[j][0], s[j][1]));
            mx1 = fmaxf(mx1, fmaxf(s[j][2], s[j][3]));
        }
        mx0 = fmaxf(mx0, __shfl_xor_sync(0xffffffffu, mx0, 1));
        mx0 = fmaxf(mx0, __shfl_xor_sync(0xffffffffu, mx0, 2));
        mx1 = fmaxf(mx1, __shfl_xor_sync(0xffffffffu, mx1, 1));
        mx1 = fmaxf(mx1, __shfl_xor_sync(0xffffffffu, mx1, 2));
        float mn0 = fmaxf(m0, mx0), mn1 = fmaxf(m1, mx1);
        float sc0 = __expf(m0 - mn0), sc1 = __expf(m1 - mn1);
        m0 = mn0; m1 = mn1;
        float ls0 = 0.f, ls1 = 0.f;
#pragma unroll
        for (int j = 0; j < 8; j++) {
            s[j][0] = __expf(s[j][0] - m0);
            s[j][1] = __expf(s[j][1] - m0);
            s[j][2] = __expf(s[j][2] - m1);
            s[j][3] = __expf(s[j][3] - m1);
            ls0 += s[j][0] + s[j][1];
            ls1 += s[j][2] + s[j][3];
        }
        ls0 += __shfl_xor_sync(0xffffffffu, ls0, 1);
        ls0 += __shfl_xor_sync(0xffffffffu, ls0, 2);
        ls1 += __shfl_xor_sync(0xffffffffu, ls1, 1);
        ls1 += __shfl_xor_sync(0xffffffffu, ls1, 2);
        l0 = l0 * sc0 + ls0;
        l1 = l1 * sc1 + ls1;
#pragma unroll
        for (int j = 0; j < 8; j++) {
            o[j][0] *= sc0; o[j][1] *= sc0;
            o[j][2] *= sc1; o[j][3] *= sc1;
        }

        // O += P @ V  (P converted to fp16 A-fragments in registers)
#pragma unroll
        for (int t = 0; t < 4; t++) {
            uint32_t p4[4];
            p4[0] = pack_h2(s[2 * t][0],     s[2 * t][1]);
            p4[1] = pack_h2(s[2 * t][2],     s[2 * t][3]);
            p4[2] = pack_h2(s[2 * t + 1][0], s[2 * t + 1][1]);
            p4[3] = pack_h2(s[2 * t + 1][2], s[2 * t + 1][3]);
#pragma unroll
            for (int g = 0; g < 4; g++) {
                uint32_t eoff = ((g * 16 + b_nof) * AQ_STR + t * 16 + b_kof) * 2;
                uint32_t v4[4];
                LDSM_X4(v4[0], v4[1], v4[2], v4[3], v_b + eoff);
                MMA_F16(o[2 * g + 0], p4, v4[0], v4[1]);
                MMA_F16(o[2 * g + 1], p4, v4[2], v4[3]);
            }
        }
        __syncthreads();
    }
#undef A_ISSUE

    // Epilogue: normalize, split, write att (split bf16) [token][h*64+d]
    const float inv0 = 1.0f / l0, inv1 = 1.0f / l1;
    const int b  = bh >> 4;
    const int hh = bh & 15;
    const int r0 = qt * 128 + w * 16 + (lane >> 2);
    const int r1 = r0 + 8;
    const int col0 = hh * HEAD_DIM + ((lane & 3) << 1);
#pragma unroll
    for (int j = 0; j < 8; j++) {
        uint32_t ph, pl;
        size_t o0 = (size_t)(b * N_SEQ + r0) * D_MODEL + col0 + 8 * j;
        split_pack2(o[j][0] * inv0, o[j][1] * inv0, ph, pl);
        *(uint32_t*)&g_att_hi[o0] = ph;
        *(uint32_t*)&g_att_lo[o0] = pl;
        size_t o1 = (size_t)(b * N_SEQ + r1) * D_MODEL + col0 + 8 * j;
        split_pack2(o[j][2] * inv1, o[j][3] * inv1, ph, pl);
        *(uint32_t*)&g_att_hi[o1] = ph;
        *(uint32_t*)&g_att_lo[o1] = pl;
    }
}

// ---------------------------------------------------------------------------
// Launch
// ---------------------------------------------------------------------------
extern "C" void kernel_launch(void* const* d_in, const int* in_sizes, int n_in,
                              void* d_out, int out_size)
{
    const float* x      = (const float*)d_in[0];
    const float* W_qkv  = (const float*)d_in[1];
    const float* b_qkv  = (const float*)d_in[2];
    const float* W_out  = (const float*)d_in[3];
    const float* b_out  = (const float*)d_in[4];
    float* out = (float*)d_out;

    static bf16 *xh = nullptr, *xl, *wqh, *wql, *woh, *wol, *ath, *atl;
    static bool init_done = false;
    if (!init_done) {
        cudaGetSymbolAddress((void**)&xh,  g_x_hi);
        cudaGetSymbolAddress((void**)&xl,  g_x_lo);
        cudaGetSymbolAddress((void**)&wqh, g_wqkv_hi);
        cudaGetSymbolAddress((void**)&wql, g_wqkv_lo);
        cudaGetSymbolAddress((void**)&woh, g_wout_hi);
        cudaGetSymbolAddress((void**)&wol, g_wout_lo);
        cudaGetSymbolAddress((void**)&ath, g_att_hi);
        cudaGetSymbolAddress((void**)&atl, g_att_lo);
        cudaFuncSetAttribute(mma_gemm_kernel,
                             cudaFuncAttributeMaxDynamicSharedMemorySize,
                             G_SMEM_B);
        cudaFuncSetAttribute(attn_mma_kernel,
                             cudaFuncAttributeMaxDynamicSharedMemorySize,
                             ATT_SMEM_BYTES);
        init_done = true;
    }

    // 0) split conversions
    {
        int n4 = (TOKENS * D_MODEL) / 4;
        split_x_kernel<<<n4 / 256, 256>>>(x, xh, xl, n4);
        dim3 blk(32, 8);
        split_wt_kernel<<<dim3(QKV_COLS / 32, D_MODEL / 32), blk>>>(W_qkv, wqh, wql, QKV_COLS, D_MODEL);
        split_wt_kernel<<<dim3(D_MODEL / 32, D_MODEL / 32), blk>>>(W_out, woh, wol, D_MODEL, D_MODEL);
    }

    // 1) QKV projection -> fp16 Q/K/Vt
    {
        dim3 grid(QKV_COLS / 128, TOKENS / 128);
        mma_gemm_kernel<<<grid, 256, G_SMEM_B>>>(xh, xl, wqh, wql, b_qkv, nullptr,
                                                 TOKENS, QKV_COLS, D_MODEL, 0);
    }

    // 2) Flash attention (fp16 mma.sync, cp.async, 2 CTA/SM) -> split att
    {
        dim3 grid(N_SEQ / 128, BH);
        attn_mma_kernel<<<grid, 256, ATT_SMEM_BYTES>>>();
    }

    // 3) Output projection -> fp32 out
    {
        dim3 grid(D_MODEL / 128, TOKENS / 128);
        mma_gemm_kernel<<<grid, 256, G_SMEM_B>>>(ath, atl, woh, wol, b_out, out,
                                                 TOKENS, D_MODEL, D_MODEL, 1);
    }
}

// round 12
// speedup vs baseline: 2.7819x; 2.7819x over previous
#include <cuda_runtime.h>
#include <cuda_fp16.h>
#include <cstdint>

// Problem constants
#define B_SZ 4
#define N_SEQ 2048
#define D_MODEL 1024
#define N_HEADS 16
#define HEAD_DIM 64
#define BH (B_SZ * N_HEADS)          // 64
#define TOKENS (B_SZ * N_SEQ)        // 8192
#define QKV_COLS (3 * D_MODEL)       // 3072

// ---------------------------------------------------------------------------
// Scratch (module-static device memory; no runtime allocation)
// ---------------------------------------------------------------------------
#define QKV_ELEMS ((size_t)BH * N_SEQ * HEAD_DIM)   // 8388608
__device__ __half g_x_f[(size_t)TOKENS * D_MODEL];
__device__ __half g_wqkv_f[(size_t)QKV_COLS * D_MODEL];   // [n][k]
__device__ __half g_wout_f[(size_t)D_MODEL * D_MODEL];    // [n][k]
__device__ __half g_q_f[QKV_ELEMS];   // [bh][n][dh], pre-scaled by 0.125
__device__ __half g_k_f[QKV_ELEMS];   // [bh][n][dh]
__device__ __half g_vt_f[QKV_ELEMS];  // [bh][dh][n]  (transposed)
__device__ __half g_att_f[(size_t)TOKENS * D_MODEL];  // [token][h*64+dh]

// ---------------------------------------------------------------------------
// Helpers
// ---------------------------------------------------------------------------
__device__ __forceinline__ uint32_t smem_u32(const void* p) {
    uint32_t a;
    asm("{ .reg .u64 t; cvta.to.shared.u64 t, %1; cvt.u32.u64 %0, t; }"
        : "=r"(a) : "l"(p));
    return a;
}

__device__ __forceinline__ uint32_t pack_h2(float x, float y) {
    __half2 h = __floats2half2_rn(x, y);
    return *(uint32_t*)&h;
}

#define LDSM_X4(r0, r1, r2, r3, addr) \
    asm volatile("ldmatrix.sync.aligned.m8n8.x4.shared.b16 {%0,%1,%2,%3}, [%4];" \
                 : "=r"(r0), "=r"(r1), "=r"(r2), "=r"(r3) : "r"(addr))

#define MMA_F16(c, a, b0, b1) \
    asm volatile("mma.sync.aligned.m16n8k16.row.col.f32.f16.f16.f32 " \
                 "{%0,%1,%2,%3}, {%4,%5,%6,%7}, {%8,%9}, {%0,%1,%2,%3};" \
                 : "+f"((c)[0]), "+f"((c)[1]), "+f"((c)[2]), "+f"((c)[3]) \
                 : "r"((a)[0]), "r"((a)[1]), "r"((a)[2]), "r"((a)[3]), \
                   "r"(b0), "r"(b1))

#define CP16(saddr, gptr) \
    asm volatile("cp.async.cg.shared.global [%0], [%1], 16;" \
                 :: "r"(saddr), "l"(gptr) : "memory")
#define CP_COMMIT() asm volatile("cp.async.commit_group;" ::: "memory")
#define CP_WAIT(n)  asm volatile("cp.async.wait_group %0;" :: "n"(n) : "memory")

// ---------------------------------------------------------------------------
// Conversion kernels (fp32 -> fp16)
// ---------------------------------------------------------------------------
__global__ void conv_x_kernel(const float* __restrict__ x, __half* __restrict__ o, int n4)
{
    int idx = blockIdx.x * 256 + threadIdx.x;
    if (idx >= n4) return;
    float4 v = ((const float4*)x)[idx];
    ((uint2*)o)[idx] = make_uint2(pack_h2(v.x, v.y), pack_h2(v.z, v.w));
}

// W[k][n] fp32 -> Wt[n][k] fp16 (tiled transpose)
__global__ void conv_wt_kernel(const float* __restrict__ W, __half* __restrict__ o,
                               int N, int K)
{
    __shared__ float t[32][33];
    const int tx = threadIdx.x, ty = threadIdx.y;  // block (32,8)
    const int n0 = blockIdx.x * 32, k0 = blockIdx.y * 32;
#pragma unroll
    for (int s = 0; s < 4; s++)
        t[ty + 8 * s][tx] = W[(size_t)(k0 + ty + 8 * s) * N + n0 + tx];
    __syncthreads();
#pragma unroll
    for (int s = 0; s < 4; s++) {
        const int nn = ty + 8 * s, kk = tx;
        o[(size_t)(n0 + nn) * K + k0 + kk] = __float2half_rn(t[kk][nn]);
    }
}

// ---------------------------------------------------------------------------
// Warp-MMA fp16 GEMM, 3-stage cp.async ring.
// C[M,N] = A[M,K] @ Bt[N,K]^T + bias[N].  BM=BN=128, BK=32, 256 thr, 8 warps.
// mode 0: QKV epilogue -> fp16 Q/K/Vt; mode 1: fp32 write + bias.
// ---------------------------------------------------------------------------
#define SSTRIDE 40
#define G_ARR_B (128 * SSTRIDE * 2)          // 10240 bytes per array
#define G_STAGE_B (2 * G_ARR_B)              // 20480 per stage (A|B)
#define G_SMEM_B (3 * G_STAGE_B)             // 61440

__global__ void __launch_bounds__(256, 2)
mma_gemm_kernel(const __half* __restrict__ A_g, const __half* __restrict__ B_g,
                const float* __restrict__ bias, float* __restrict__ C,
                int M, int N, int K, int mode)
{
    extern __shared__ __align__(16) char dsm[];
    const uint32_t sb0 = smem_u32(dsm);

    const int tid  = threadIdx.x;
    const int wid  = tid >> 5;
    const int lane = tid & 31;
    const int wr   = wid >> 1;
    const int wc   = wid & 1;

    const int row0 = blockIdx.y * 128;
    const int col0 = blockIdx.x * 128;

    float acc[2][8][4];
#pragma unroll
    for (int i = 0; i < 2; i++)
#pragma unroll
        for (int j = 0; j < 8; j++)
#pragma unroll
            for (int c = 0; c < 4; c++) acc[i][j][c] = 0.f;

    const uint32_t a_row = lane & 15;
    const uint32_t a_kof = (lane >> 4) << 3;
    const uint32_t b_nof = ((lane >> 4) << 3) + (lane & 7);
    const uint32_t b_kof = ((lane >> 3) & 1) << 3;

    const int f0 = tid, f1 = 256 + tid;
    const int r_0 = f0 >> 2, c8_0 = (f0 & 3) << 3;
    const int r_1 = f1 >> 2, c8_1 = (f1 & 3) << 3;
    const uint32_t so_0 = ((uint32_t)r_0 * SSTRIDE + c8_0) * 2;
    const uint32_t so_1 = ((uint32_t)r_1 * SSTRIDE + c8_1) * 2;

#define G_ISSUE(stage, k0_)                                                     \
    do {                                                                        \
        uint32_t sb = sb0 + (stage) * G_STAGE_B;                                \
        CP16(sb + so_0,           A_g + (size_t)(row0 + r_0) * K + (k0_) + c8_0); \
        CP16(sb + so_1,           A_g + (size_t)(row0 + r_1) * K + (k0_) + c8_1); \
        CP16(sb + G_ARR_B + so_0, B_g + (size_t)(col0 + r_0) * K + (k0_) + c8_0); \
        CP16(sb + G_ARR_B + so_1, B_g + (size_t)(col0 + r_1) * K + (k0_) + c8_1); \
        CP_COMMIT();                                                            \
    } while (0)

    const int niter = K / 32;
    G_ISSUE(0, 0);
    G_ISSUE(1, 32);

    for (int it = 0; it < niter; it++) {
        if (it + 1 < niter) { CP_WAIT(1); } else { CP_WAIT(0); }
        __syncthreads();

        const uint32_t sb  = sb0 + (it % 3) * G_STAGE_B;
        const uint32_t a_b = sb;
        const uint32_t b_b = sb + G_ARR_B;

#pragma unroll
        for (int ks = 0; ks < 2; ks++) {
            const uint32_t kk = ks * 16;
            uint32_t ar[2][4];
#pragma unroll
            for (int i = 0; i < 2; i++) {
                uint32_t eoff = ((wr * 32 + i * 16 + a_row) * SSTRIDE + kk + a_kof) * 2;
                LDSM_X4(ar[i][0], ar[i][1], ar[i][2], ar[i][3], a_b + eoff);
            }
#pragma unroll
            for (int jp = 0; jp < 4; jp++) {
                const uint32_t nb = wc * 64 + jp * 16;
                uint32_t eoff = ((nb + b_nof) * SSTRIDE + kk + b_kof) * 2;
                uint32_t br[4];
                LDSM_X4(br[0], br[1], br[2], br[3], b_b + eoff);
#pragma unroll
                for (int i = 0; i < 2; i++) {
                    MMA_F16(acc[i][2 * jp + 0], ar[i], br[0], br[1]);
                    MMA_F16(acc[i][2 * jp + 1], ar[i], br[2], br[3]);
                }
            }
        }
        if (it + 2 < niter) G_ISSUE((it + 2) % 3, (it + 2) * 32);
    }
#undef G_ISSUE

    const int mbase = row0 + wr * 32 + (lane >> 2);
    const int nbase = col0 + wc * 64 + ((lane & 3) << 1);

    if (mode == 0) {
#pragma unroll
        for (int i = 0; i < 2; i++) {
#pragma unroll
            for (int rr = 0; rr < 2; rr++) {
                const int m  = mbase + i * 16 + rr * 8;
                const int bb = m >> 11;
                const int nn = m & 2047;
#pragma unroll
                for (int j = 0; j < 8; j++) {
                    const int jg0 = nbase + j * 8;
                    const int sel = jg0 >> 10;
                    const int hh  = (jg0 >> 6) & 15;
                    const int dh  = jg0 & 63;
                    const int bhd = bb * N_HEADS + hh;
                    float v0 = acc[i][j][rr * 2 + 0] + bias[jg0];
                    float v1 = acc[i][j][rr * 2 + 1] + bias[jg0 + 1];
                    if (sel == 0) { v0 *= 0.125f; v1 *= 0.125f; }
                    if (sel == 0) {
                        size_t o = ((size_t)bhd * N_SEQ + nn) * HEAD_DIM + dh;
                        *(uint32_t*)&g_q_f[o] = pack_h2(v0, v1);
                    } else if (sel == 1) {
                        size_t o = ((size_t)bhd * N_SEQ + nn) * HEAD_DIM + dh;
                        *(uint32_t*)&g_k_f[o] = pack_h2(v0, v1);
                    } else {
                        size_t o = ((size_t)bhd * HEAD_DIM + dh) * N_SEQ + nn;
                        g_vt_f[o] = __float2half_rn(v0);
                        g_vt_f[o + N_SEQ] = __float2half_rn(v1);
                    }
                }
            }
        }
    } else {
#pragma unroll
        for (int i = 0; i < 2; i++) {
#pragma unroll
            for (int rr = 0; rr < 2; rr++) {
                const int m = mbase + i * 16 + rr * 8;
                float* cp = C + (size_t)m * N;
#pragma unroll
                for (int j = 0; j < 8; j++) {
#pragma unroll
                    for (int c = 0; c < 2; c++) {
                        const int jg = nbase + j * 8 + c;
                        cp[jg] = acc[i][j][rr * 2 + c] + bias[jg];
                    }
                }
            }
        }
    }
}

// ---------------------------------------------------------------------------
// mma.sync fp16 flash attention, 3-stage cp.async KV ring, 2 CTAs/SM.
// CTA: (head bh, 128-query tile). 8 warps x m16. fp32 accumulation.
// smem: Q [128][72] fp16 + 3 stages x (K|V) [64][72] fp16 = 73728 B.
// ---------------------------------------------------------------------------
#define AQ_STR 72
#define A_Q_ARR_B (128 * AQ_STR * 2)     // 18432
#define A_KV_ARR_B (64 * AQ_STR * 2)     // 9216
#define A_KV_STAGE_B (2 * A_KV_ARR_B)    // 18432
#define A_KV_BASE A_Q_ARR_B              // 18432
#define ATT_SMEM_BYTES (A_KV_BASE + 3 * A_KV_STAGE_B)   // 73728

__global__ void __launch_bounds__(256, 2)
attn_mma_kernel()
{
    extern __shared__ __align__(16) char dsm[];
    const uint32_t sb0  = smem_u32(dsm);
    const uint32_t q_b  = sb0;

    const int tid  = threadIdx.x;
    const int w    = tid >> 5;
    const int lane = tid & 31;
    const int bh   = blockIdx.y;
    const int qt   = blockIdx.x;

    const __half* ksrc = g_k_f + (size_t)bh * N_SEQ * HEAD_DIM;
    const __half* vsrc = g_vt_f + (size_t)bh * HEAD_DIM * N_SEQ;

    const int f0 = tid, f1 = 256 + tid;
    const int kr0 = f0 >> 3, kc0 = (f0 & 7) << 3;
    const int kr1 = f1 >> 3, kc1 = (f1 & 7) << 3;
    const uint32_t kso0 = ((uint32_t)kr0 * AQ_STR + kc0) * 2;
    const uint32_t kso1 = ((uint32_t)kr1 * AQ_STR + kc1) * 2;

#define A_ISSUE(stage, kt_)                                                     \
    do {                                                                        \
        uint32_t sb = sb0 + A_KV_BASE + (stage) * A_KV_STAGE_B;                 \
        CP16(sb + kso0,               ksrc + (size_t)((kt_) * 64 + kr0) * HEAD_DIM + kc0); \
        CP16(sb + kso1,               ksrc + (size_t)((kt_) * 64 + kr1) * HEAD_DIM + kc1); \
        CP16(sb + A_KV_ARR_B + kso0,  vsrc + (size_t)kr0 * N_SEQ + (kt_) * 64 + kc0); \
        CP16(sb + A_KV_ARR_B + kso1,  vsrc + (size_t)kr1 * N_SEQ + (kt_) * 64 + kc1); \
        CP_COMMIT();                                                            \
    } while (0)

    A_ISSUE(0, 0);
    A_ISSUE(1, 1);

    // Load Q tile [128][64] fp16 (plain loads, once)
    const __half* qsrc = g_q_f + ((size_t)bh * N_SEQ + qt * 128) * HEAD_DIM;
#pragma unroll
    for (int i = 0; i < 4; i++) {
        int f  = i * 256 + tid;
        int r  = f >> 3;
        int c8 = (f & 7) << 3;
        uint32_t so = ((uint32_t)r * AQ_STR + c8) * 2;
        *(uint4*)(dsm + so) = *(const uint4*)(qsrc + r * HEAD_DIM + c8);
    }

    const uint32_t a_row = lane & 15;
    const uint32_t a_kof = (lane >> 4) << 3;
    const uint32_t b_nof = ((lane >> 4) << 3) + (lane & 7);
    const uint32_t b_kof = ((lane >> 3) & 1) << 3;

    float m0 = -1e30f, m1 = -1e30f, l0 = 0.f, l1 = 0.f;
    float o[8][4];
#pragma unroll
    for (int j = 0; j < 8; j++)
#pragma unroll
        for (int c = 0; c < 4; c++) o[j][c] = 0.f;

    const int nkt = N_SEQ / 64;
    for (int kt = 0; kt < nkt; kt++) {
        if (kt + 1 < nkt) { CP_WAIT(1); } else { CP_WAIT(0); }
        __syncthreads();

        const uint32_t sb  = sb0 + A_KV_BASE + (kt % 3) * A_KV_STAGE_B;
        const uint32_t k_b = sb;
        const uint32_t v_b = sb + A_KV_ARR_B;

        // S = Q @ K^T (scale pre-folded into Q)
        float s[8][4];
#pragma unroll
        for (int j = 0; j < 8; j++)
#pragma unroll
            for (int c = 0; c < 4; c++) s[j][c] = 0.f;

#pragma unroll
        for (int t = 0; t < 4; t++) {
            uint32_t q4[4];
            {
                uint32_t eoff = ((w * 16 + a_row) * AQ_STR + t * 16 + a_kof) * 2;
                LDSM_X4(q4[0], q4[1], q4[2], q4[3], q_b + eoff);
            }
#pragma unroll
            for (int g = 0; g < 4; g++) {
                uint32_t eoff = ((g * 16 + b_nof) * AQ_STR + t * 16 + b_kof) * 2;
                uint32_t k4[4];
                LDSM_X4(k4[0], k4[1], k4[2], k4[3], k_b + eoff);
                MMA_F16(s[2 * g + 0], q4, k4[0], k4[1]);
                MMA_F16(s[2 * g + 1], q4, k4[2], k4[3]);
            }
        }

        // Online softmax
        float mx0 = -1e30f, mx1 = -1e30f;
#pragma unroll
        for (int j = 0; j < 8; j++) {
            mx0 = fmaxf(mx0, fmaxf(s[j][0], s[j][1]));
            mx1 = fmaxf(mx1, fmaxf(s[j][2], s[j][3]));
        }
        mx0 = fmaxf(mx0, __shfl_xor_sync(0xffffffffu, mx0, 1));
        mx0 = fmaxf(mx0, __shfl_xor_sync(0xffffffffu, mx0, 2));
        mx1 = fmaxf(mx1, __shfl_xor_sync(0xffffffffu, mx1, 1));
        mx1 = fmaxf(mx1, __shfl_xor_sync(0xffffffffu, mx1, 2));
        float mn0 = fmaxf(m0, mx0), mn1 = fmaxf(m1, mx1);
        float sc0 = __expf(m0 - mn0), sc1 = __expf(m1 - mn1);
        m0 = mn0; m1 = mn1;
        float ls0 = 0.f, ls1 = 0.f;
#pragma unroll
        for (int j = 0; j < 8; j++) {
            s[j][0] = __expf(s[j][0] - m0);
            s[j][1] = __expf(s[j][1] - m0);
            s[j][2] = __expf(s[j][2] - m1);
            s[j][3] = __expf(s[j][3] - m1);
            ls0 += s[j][0] + s[j][1];
            ls1 += s[j][2] + s[j][3];
        }
        ls0 += __shfl_xor_sync(0xffffffffu, ls0, 1);
        ls0 += __shfl_xor_sync(0xffffffffu, ls0, 2);
        ls1 += __shfl_xor_sync(0xffffffffu, ls1, 1);
        ls1 += __shfl_xor_sync(0xffffffffu, ls1, 2);
        l0 = l0 * sc0 + ls0;
        l1 = l1 * sc1 + ls1;
#pragma unroll
        for (int j = 0; j < 8; j++) {
            o[j][0] *= sc0; o[j][1] *= sc0;
            o[j][2] *= sc1; o[j][3] *= sc1;
        }

        // O += P @ V  (P converted to fp16 A-fragments in registers)
#pragma unroll
        for (int t = 0; t < 4; t++) {
            uint32_t p4[4];
            p4[0] = pack_h2(s[2 * t][0],     s[2 * t][1]);
            p4[1] = pack_h2(s[2 * t][2],     s[2 * t][3]);
            p4[2] = pack_h2(s[2 * t + 1][0], s[2 * t + 1][1]);
            p4[3] = pack_h2(s[2 * t + 1][2], s[2 * t + 1][3]);
#pragma unroll
            for (int g = 0; g < 4; g++) {
                uint32_t eoff = ((g * 16 + b_nof) * AQ_STR + t * 16 + b_kof) * 2;
                uint32_t v4[4];
                LDSM_X4(v4[0], v4[1], v4[2], v4[3], v_b + eoff);
                MMA_F16(o[2 * g + 0], p4, v4[0], v4[1]);
                MMA_F16(o[2 * g + 1], p4, v4[2], v4[3]);
            }
        }
        if (kt + 2 < nkt) A_ISSUE((kt + 2) % 3, kt + 2);
    }
#undef A_ISSUE

    // Epilogue: normalize, write att fp16 [token][h*64+d]
    const float inv0 = 1.0f / l0, inv1 = 1.0f / l1;
    const int b  = bh >> 4;
    const int hh = bh & 15;
    const int r0 = qt * 128 + w * 16 + (lane >> 2);
    const int r1 = r0 + 8;
    const int col0 = hh * HEAD_DIM + ((lane & 3) << 1);
#pragma unroll
    for (int j = 0; j < 8; j++) {
        size_t o0 = (size_t)(b * N_SEQ + r0) * D_MODEL + col0 + 8 * j;
        *(uint32_t*)&g_att_f[o0] = pack_h2(o[j][0] * inv0, o[j][1] * inv0);
        size_t o1 = (size_t)(b * N_SEQ + r1) * D_MODEL + col0 + 8 * j;
        *(uint32_t*)&g_att_f[o1] = pack_h2(o[j][2] * inv1, o[j][3] * inv1);
    }
}

// ---------------------------------------------------------------------------
// Launch
// ---------------------------------------------------------------------------
extern "C" void kernel_launch(void* const* d_in, const int* in_sizes, int n_in,
                              void* d_out, int out_size)
{
    const float* x      = (const float*)d_in[0];
    const float* W_qkv  = (const float*)d_in[1];
    const float* b_qkv  = (const float*)d_in[2];
    const float* W_out  = (const float*)d_in[3];
    const float* b_out  = (const float*)d_in[4];
    float* out = (float*)d_out;

    static __half *xf = nullptr, *wqf, *wof, *atf;
    static bool init_done = false;
    if (!init_done) {
        cudaGetSymbolAddress((void**)&xf,  g_x_f);
        cudaGetSymbolAddress((void**)&wqf, g_wqkv_f);
        cudaGetSymbolAddress((void**)&wof, g_wout_f);
        cudaGetSymbolAddress((void**)&atf, g_att_f);
        cudaFuncSetAttribute(mma_gemm_kernel,
                             cudaFuncAttributeMaxDynamicSharedMemorySize,
                             G_SMEM_B);
        cudaFuncSetAttribute(attn_mma_kernel,
                             cudaFuncAttributeMaxDynamicSharedMemorySize,
                             ATT_SMEM_BYTES);
        init_done = true;
    }

    // 0) fp16 conversions
    {
        int n4 = (TOKENS * D_MODEL) / 4;
        conv_x_kernel<<<n4 / 256, 256>>>(x, xf, n4);
        dim3 blk(32, 8);
        conv_wt_kernel<<<dim3(QKV_COLS / 32, D_MODEL / 32), blk>>>(W_qkv, wqf, QKV_COLS, D_MODEL);
        conv_wt_kernel<<<dim3(D_MODEL / 32, D_MODEL / 32), blk>>>(W_out, wof, D_MODEL, D_MODEL);
    }

    // 1) QKV projection -> fp16 Q/K/Vt
    {
        dim3 grid(QKV_COLS / 128, TOKENS / 128);
        mma_gemm_kernel<<<grid, 256, G_SMEM_B>>>(xf, wqf, b_qkv, nullptr,
                                                 TOKENS, QKV_COLS, D_MODEL, 0);
    }

    // 2) Flash attention (fp16 mma.sync, 3-stage cp.async, 2 CTA/SM)
    {
        dim3 grid(N_SEQ / 128, BH);
        attn_mma_kernel<<<grid, 256, ATT_SMEM_BYTES>>>();
    }

    // 3) Output projection -> fp32 out
    {
        dim3 grid(D_MODEL / 128, TOKENS / 128);
        mma_gemm_kernel<<<grid, 256, G_SMEM_B>>>(atf, wof, b_out, out,
                                                 TOKENS, D_MODEL, D_MODEL, 1);
    }
}

// round 13
// speedup vs baseline: 3.0559x; 1.0985x over previous
#include <cuda_runtime.h>
#include <cuda_fp16.h>
#include <cstdint>

// Problem constants
#define B_SZ 4
#define N_SEQ 2048
#define D_MODEL 1024
#define N_HEADS 16
#define HEAD_DIM 64
#define BH (B_SZ * N_HEADS)          // 64
#define TOKENS (B_SZ * N_SEQ)        // 8192
#define QKV_COLS (3 * D_MODEL)       // 3072

// ---------------------------------------------------------------------------
// Scratch (module-static device memory; no runtime allocation)
// ---------------------------------------------------------------------------
#define QKV_ELEMS ((size_t)BH * N_SEQ * HEAD_DIM)   // 8388608
__device__ __half g_x_f[(size_t)TOKENS * D_MODEL];
__device__ __half g_wqkv_f[(size_t)QKV_COLS * D_MODEL];   // [n][k]
__device__ __half g_wout_f[(size_t)D_MODEL * D_MODEL];    // [n][k]
__device__ __half g_q_f[QKV_ELEMS];   // [bh][n][dh], pre-scaled by 0.125*log2(e)
__device__ __half g_k_f[QKV_ELEMS];   // [bh][n][dh]
__device__ __half g_vt_f[QKV_ELEMS];  // [bh][dh][n]  (transposed)
__device__ __half g_att_f[(size_t)TOKENS * D_MODEL];  // [token][h*64+dh]

// ---------------------------------------------------------------------------
// Helpers
// ---------------------------------------------------------------------------
__device__ __forceinline__ uint32_t smem_u32(const void* p) {
    uint32_t a;
    asm("{ .reg .u64 t; cvta.to.shared.u64 t, %1; cvt.u32.u64 %0, t; }"
        : "=r"(a) : "l"(p));
    return a;
}

__device__ __forceinline__ uint32_t pack_h2(float x, float y) {
    __half2 h = __floats2half2_rn(x, y);
    return *(uint32_t*)&h;
}

__device__ __forceinline__ float fexp2(float x) {
    float y;
    asm("ex2.approx.f32 %0, %1;" : "=f"(y) : "f"(x));
    return y;
}

#define LDSM_X4(r0, r1, r2, r3, addr) \
    asm volatile("ldmatrix.sync.aligned.m8n8.x4.shared.b16 {%0,%1,%2,%3}, [%4];" \
                 : "=r"(r0), "=r"(r1), "=r"(r2), "=r"(r3) : "r"(addr))

#define MMA_F16(c, a, b0, b1) \
    asm volatile("mma.sync.aligned.m16n8k16.row.col.f32.f16.f16.f32 " \
                 "{%0,%1,%2,%3}, {%4,%5,%6,%7}, {%8,%9}, {%0,%1,%2,%3};" \
                 : "+f"((c)[0]), "+f"((c)[1]), "+f"((c)[2]), "+f"((c)[3]) \
                 : "r"((a)[0]), "r"((a)[1]), "r"((a)[2]), "r"((a)[3]), \
                   "r"(b0), "r"(b1))

#define CP16(saddr, gptr) \
    asm volatile("cp.async.cg.shared.global [%0], [%1], 16;" \
                 :: "r"(saddr), "l"(gptr) : "memory")
#define CP_COMMIT() asm volatile("cp.async.commit_group;" ::: "memory")
#define CP_WAIT(n)  asm volatile("cp.async.wait_group %0;" :: "n"(n) : "memory")

// Q pre-scale: (1/sqrt(64)) * log2(e), so softmax runs in base-2 domain.
#define Q_SCALE 0.1803368801111244f

// ---------------------------------------------------------------------------
// Conversion kernels (fp32 -> fp16)
// ---------------------------------------------------------------------------
__global__ void conv_x_kernel(const float* __restrict__ x, __half* __restrict__ o, int n4)
{
    int idx = blockIdx.x * 256 + threadIdx.x;
    if (idx >= n4) return;
    float4 v = ((const float4*)x)[idx];
    ((uint2*)o)[idx] = make_uint2(pack_h2(v.x, v.y), pack_h2(v.z, v.w));
}

// W[k][n] fp32 -> Wt[n][k] fp16 (tiled transpose)
__global__ void conv_wt_kernel(const float* __restrict__ W, __half* __restrict__ o,
                               int N, int K)
{
    __shared__ float t[32][33];
    const int tx = threadIdx.x, ty = threadIdx.y;  // block (32,8)
    const int n0 = blockIdx.x * 32, k0 = blockIdx.y * 32;
#pragma unroll
    for (int s = 0; s < 4; s++)
        t[ty + 8 * s][tx] = W[(size_t)(k0 + ty + 8 * s) * N + n0 + tx];
    __syncthreads();
#pragma unroll
    for (int s = 0; s < 4; s++) {
        const int nn = ty + 8 * s, kk = tx;
        o[(size_t)(n0 + nn) * K + k0 + kk] = __float2half_rn(t[kk][nn]);
    }
}

// ---------------------------------------------------------------------------
// Warp-MMA fp16 GEMM, BK=64, 3-stage cp.async ring (one barrier per iter).
// C[M,N] = A[M,K] @ Bt[N,K]^T + bias[N].  BM=BN=128, 256 thr, 8 warps.
// mode 0: QKV epilogue -> fp16 Q/K/Vt; mode 1: fp32 write + bias.
// ---------------------------------------------------------------------------
#define SSTRIDE 72
#define G_ARR_B (128 * SSTRIDE * 2)          // 18432 bytes per array (128x64 fp16)
#define G_STAGE_B (2 * G_ARR_B)              // 36864 per stage (A|B)
#define G_SMEM_B (3 * G_STAGE_B)             // 110592

__global__ void __launch_bounds__(256, 2)
mma_gemm_kernel(const __half* __restrict__ A_g, const __half* __restrict__ B_g,
                const float* __restrict__ bias, float* __restrict__ C,
                int M, int N, int K, int mode)
{
    extern __shared__ __align__(16) char dsm[];
    const uint32_t sb0 = smem_u32(dsm);

    const int tid  = threadIdx.x;
    const int wid  = tid >> 5;
    const int lane = tid & 31;
    const int wr   = wid >> 1;
    const int wc   = wid & 1;

    const int row0 = blockIdx.y * 128;
    const int col0 = blockIdx.x * 128;

    float acc[2][8][4];
#pragma unroll
    for (int i = 0; i < 2; i++)
#pragma unroll
        for (int j = 0; j < 8; j++)
#pragma unroll
            for (int c = 0; c < 4; c++) acc[i][j][c] = 0.f;

    const uint32_t a_row = lane & 15;
    const uint32_t a_kof = (lane >> 4) << 3;
    const uint32_t b_nof = ((lane >> 4) << 3) + (lane & 7);
    const uint32_t b_kof = ((lane >> 3) & 1) << 3;

    // Load coords: 1024 16B chunks per array, 4 per thread
    int lr[4], lc[4];
    uint32_t lso[4];
#pragma unroll
    for (int i = 0; i < 4; i++) {
        int f = i * 256 + tid;
        lr[i] = f >> 3;
        lc[i] = (f & 7) << 3;
        lso[i] = ((uint32_t)lr[i] * SSTRIDE + lc[i]) * 2;
    }

#define G_ISSUE(stage, k0_)                                                     \
    do {                                                                        \
        uint32_t sb = sb0 + (stage) * G_STAGE_B;                                \
        _Pragma("unroll")                                                       \
        for (int i = 0; i < 4; i++) {                                           \
            CP16(sb + lso[i],           A_g + (size_t)(row0 + lr[i]) * K + (k0_) + lc[i]); \
            CP16(sb + G_ARR_B + lso[i], B_g + (size_t)(col0 + lr[i]) * K + (k0_) + lc[i]); \
        }                                                                       \
        CP_COMMIT();                                                            \
    } while (0)

    const int niter = K / 64;
    G_ISSUE(0, 0);
    G_ISSUE(1, 64);

    for (int it = 0; it < niter; it++) {
        if (it + 1 < niter) { CP_WAIT(1); } else { CP_WAIT(0); }
        __syncthreads();

        const uint32_t sb  = sb0 + (it % 3) * G_STAGE_B;
        const uint32_t a_b = sb;
        const uint32_t b_b = sb + G_ARR_B;

#pragma unroll
        for (int ks = 0; ks < 4; ks++) {
            const uint32_t kk = ks * 16;
            uint32_t ar[2][4];
#pragma unroll
            for (int i = 0; i < 2; i++) {
                uint32_t eoff = ((wr * 32 + i * 16 + a_row) * SSTRIDE + kk + a_kof) * 2;
                LDSM_X4(ar[i][0], ar[i][1], ar[i][2], ar[i][3], a_b + eoff);
            }
#pragma unroll
            for (int jp = 0; jp < 4; jp++) {
                const uint32_t nb = wc * 64 + jp * 16;
                uint32_t eoff = ((nb + b_nof) * SSTRIDE + kk + b_kof) * 2;
                uint32_t br[4];
                LDSM_X4(br[0], br[1], br[2], br[3], b_b + eoff);
#pragma unroll
                for (int i = 0; i < 2; i++) {
                    MMA_F16(acc[i][2 * jp + 0], ar[i], br[0], br[1]);
                    MMA_F16(acc[i][2 * jp + 1], ar[i], br[2], br[3]);
                }
            }
        }
        if (it + 2 < niter) G_ISSUE((it + 2) % 3, (it + 2) * 64);
    }
#undef G_ISSUE

    const int mbase = row0 + wr * 32 + (lane >> 2);
    const int nbase = col0 + wc * 64 + ((lane & 3) << 1);

    if (mode == 0) {
#pragma unroll
        for (int i = 0; i < 2; i++) {
#pragma unroll
            for (int rr = 0; rr < 2; rr++) {
                const int m  = mbase + i * 16 + rr * 8;
                const int bb = m >> 11;
                const int nn = m & 2047;
#pragma unroll
                for (int j = 0; j < 8; j++) {
                    const int jg0 = nbase + j * 8;
                    const int sel = jg0 >> 10;
                    const int hh  = (jg0 >> 6) & 15;
                    const int dh  = jg0 & 63;
                    const int bhd = bb * N_HEADS + hh;
                    float v0 = acc[i][j][rr * 2 + 0] + bias[jg0];
                    float v1 = acc[i][j][rr * 2 + 1] + bias[jg0 + 1];
                    if (sel == 0) { v0 *= Q_SCALE; v1 *= Q_SCALE; }
                    if (sel == 0) {
                        size_t o = ((size_t)bhd * N_SEQ + nn) * HEAD_DIM + dh;
                        *(uint32_t*)&g_q_f[o] = pack_h2(v0, v1);
                    } else if (sel == 1) {
                        size_t o = ((size_t)bhd * N_SEQ + nn) * HEAD_DIM + dh;
                        *(uint32_t*)&g_k_f[o] = pack_h2(v0, v1);
                    } else {
                        size_t o = ((size_t)bhd * HEAD_DIM + dh) * N_SEQ + nn;
                        g_vt_f[o] = __float2half_rn(v0);
                        g_vt_f[o + N_SEQ] = __float2half_rn(v1);
                    }
                }
            }
        }
    } else {
#pragma unroll
        for (int i = 0; i < 2; i++) {
#pragma unroll
            for (int rr = 0; rr < 2; rr++) {
                const int m = mbase + i * 16 + rr * 8;
                float* cp = C + (size_t)m * N;
#pragma unroll
                for (int j = 0; j < 8; j++) {
#pragma unroll
                    for (int c = 0; c < 2; c++) {
                        const int jg = nbase + j * 8 + c;
                        cp[jg] = acc[i][j][rr * 2 + c] + bias[jg];
                    }
                }
            }
        }
    }
}

// ---------------------------------------------------------------------------
// mma.sync fp16 flash attention, 3-stage cp.async KV ring, 2 CTAs/SM.
// Base-2 online softmax (log2e folded into Q); denominator reduced at end.
// smem: Q [128][72] fp16 + 3 stages x (K|V) [64][72] fp16 = 73728 B.
// ---------------------------------------------------------------------------
#define AQ_STR 72
#define A_Q_ARR_B (128 * AQ_STR * 2)     // 18432
#define A_KV_ARR_B (64 * AQ_STR * 2)     // 9216
#define A_KV_STAGE_B (2 * A_KV_ARR_B)    // 18432
#define A_KV_BASE A_Q_ARR_B              // 18432
#define ATT_SMEM_BYTES (A_KV_BASE + 3 * A_KV_STAGE_B)   // 73728

__global__ void __launch_bounds__(256, 2)
attn_mma_kernel()
{
    extern __shared__ __align__(16) char dsm[];
    const uint32_t sb0  = smem_u32(dsm);
    const uint32_t q_b  = sb0;

    const int tid  = threadIdx.x;
    const int w    = tid >> 5;
    const int lane = tid & 31;
    const int bh   = blockIdx.y;
    const int qt   = blockIdx.x;

    const __half* ksrc = g_k_f + (size_t)bh * N_SEQ * HEAD_DIM;
    const __half* vsrc = g_vt_f + (size_t)bh * HEAD_DIM * N_SEQ;

    const int f0 = tid, f1 = 256 + tid;
    const int kr0 = f0 >> 3, kc0 = (f0 & 7) << 3;
    const int kr1 = f1 >> 3, kc1 = (f1 & 7) << 3;
    const uint32_t kso0 = ((uint32_t)kr0 * AQ_STR + kc0) * 2;
    const uint32_t kso1 = ((uint32_t)kr1 * AQ_STR + kc1) * 2;

#define A_ISSUE(stage, kt_)                                                     \
    do {                                                                        \
        uint32_t sb = sb0 + A_KV_BASE + (stage) * A_KV_STAGE_B;                 \
        CP16(sb + kso0,               ksrc + (size_t)((kt_) * 64 + kr0) * HEAD_DIM + kc0); \
        CP16(sb + kso1,               ksrc + (size_t)((kt_) * 64 + kr1) * HEAD_DIM + kc1); \
        CP16(sb + A_KV_ARR_B + kso0,  vsrc + (size_t)kr0 * N_SEQ + (kt_) * 64 + kc0); \
        CP16(sb + A_KV_ARR_B + kso1,  vsrc + (size_t)kr1 * N_SEQ + (kt_) * 64 + kc1); \
        CP_COMMIT();                                                            \
    } while (0)

    A_ISSUE(0, 0);
    A_ISSUE(1, 1);

    // Load Q tile [128][64] fp16 (plain loads, once)
    const __half* qsrc = g_q_f + ((size_t)bh * N_SEQ + qt * 128) * HEAD_DIM;
#pragma unroll
    for (int i = 0; i < 4; i++) {
        int f  = i * 256 + tid;
        int r  = f >> 3;
        int c8 = (f & 7) << 3;
        uint32_t so = ((uint32_t)r * AQ_STR + c8) * 2;
        *(uint4*)(dsm + so) = *(const uint4*)(qsrc + r * HEAD_DIM + c8);
    }

    const uint32_t a_row = lane & 15;
    const uint32_t a_kof = (lane >> 4) << 3;
    const uint32_t b_nof = ((lane >> 4) << 3) + (lane & 7);
    const uint32_t b_kof = ((lane >> 3) & 1) << 3;

    float m0 = -1e30f, m1 = -1e30f, l0 = 0.f, l1 = 0.f;
    float o[8][4];
#pragma unroll
    for (int j = 0; j < 8; j++)
#pragma unroll
        for (int c = 0; c < 4; c++) o[j][c] = 0.f;

    const int nkt = N_SEQ / 64;
    for (int kt = 0; kt < nkt; kt++) {
        if (kt + 1 < nkt) { CP_WAIT(1); } else { CP_WAIT(0); }
        __syncthreads();

        const uint32_t sb  = sb0 + A_KV_BASE + (kt % 3) * A_KV_STAGE_B;
        const uint32_t k_b = sb;
        const uint32_t v_b = sb + A_KV_ARR_B;

        // S = Q @ K^T (base-2 scale pre-folded into Q)
        float s[8][4];
#pragma unroll
        for (int j = 0; j < 8; j++)
#pragma unroll
            for (int c = 0; c < 4; c++) s[j][c] = 0.f;

#pragma unroll
        for (int t = 0; t < 4; t++) {
            uint32_t q4[4];
            {
                uint32_t eoff = ((w * 16 + a_row) * AQ_STR + t * 16 + a_kof) * 2;
                LDSM_X4(q4[0], q4[1], q4[2], q4[3], q_b + eoff);
            }
#pragma unroll
            for (int g = 0; g < 4; g++) {
                uint32_t eoff = ((g * 16 + b_nof) * AQ_STR + t * 16 + b_kof) * 2;
                uint32_t k4[4];
                LDSM_X4(k4[0], k4[1], k4[2], k4[3], k_b + eoff);
                MMA_F16(s[2 * g + 0], q4, k4[0], k4[1]);
                MMA_F16(s[2 * g + 1], q4, k4[2], k4[3]);
            }
        }

        // Online softmax (base-2). Row max shared by 4-lane groups; l kept
        // per-thread (sc uniform within group) and reduced once at the end.
        float mx0 = -1e30f, mx1 = -1e30f;
#pragma unroll
        for (int j = 0; j < 8; j++) {
            mx0 = fmaxf(mx0, fmaxf(s[j][0], s[j][1]));
            mx1 = fmaxf(mx1, fmaxf(s[j][2], s[j][3]));
        }
        mx0 = fmaxf(mx0, __shfl_xor_sync(0xffffffffu, mx0, 1));
        mx0 = fmaxf(mx0, __shfl_xor_sync(0xffffffffu, mx0, 2));
        mx1 = fmaxf(mx1, __shfl_xor_sync(0xffffffffu, mx1, 1));
        mx1 = fmaxf(mx1, __shfl_xor_sync(0xffffffffu, mx1, 2));
        float mn0 = fmaxf(m0, mx0), mn1 = fmaxf(m1, mx1);
        float sc0 = fexp2(m0 - mn0), sc1 = fexp2(m1 - mn1);
        m0 = mn0; m1 = mn1;
        float ls0 = 0.f, ls1 = 0.f;
#pragma unroll
        for (int j = 0; j < 8; j++) {
            s[j][0] = fexp2(s[j][0] - m0);
            s[j][1] = fexp2(s[j][1] - m0);
            s[j][2] = fexp2(s[j][2] - m1);
            s[j][3] = fexp2(s[j][3] - m1);
            ls0 += s[j][0] + s[j][1];
            ls1 += s[j][2] + s[j][3];
        }
        l0 = l0 * sc0 + ls0;
        l1 = l1 * sc1 + ls1;
#pragma unroll
        for (int j = 0; j < 8; j++) {
            o[j][0] *= sc0; o[j][1] *= sc0;
            o[j][2] *= sc1; o[j][3] *= sc1;
        }

        // O += P @ V  (P converted to fp16 A-fragments in registers)
#pragma unroll
        for (int t = 0; t < 4; t++) {
            uint32_t p4[4];
            p4[0] = pack_h2(s[2 * t][0],     s[2 * t][1]);
            p4[1] = pack_h2(s[2 * t][2],     s[2 * t][3]);
            p4[2] = pack_h2(s[2 * t + 1][0], s[2 * t + 1][1]);
            p4[3] = pack_h2(s[2 * t + 1][2], s[2 * t + 1][3]);
#pragma unroll
            for (int g = 0; g < 4; g++) {
                uint32_t eoff = ((g * 16 + b_nof) * AQ_STR + t * 16 + b_kof) * 2;
                uint32_t v4[4];
                LDSM_X4(v4[0], v4[1], v4[2], v4[3], v_b + eoff);
                MMA_F16(o[2 * g + 0], p4, v4[0], v4[1]);
                MMA_F16(o[2 * g + 1], p4, v4[2], v4[3]);
            }
        }
        if (kt + 2 < nkt) A_ISSUE((kt + 2) % 3, kt + 2);
    }
#undef A_ISSUE

    // Final denominator reduction across the 4-lane row group
    l0 += __shfl_xor_sync(0xffffffffu, l0, 1);
    l0 += __shfl_xor_sync(0xffffffffu, l0, 2);
    l1 += __shfl_xor_sync(0xffffffffu, l1, 1);
    l1 += __shfl_xor_sync(0xffffffffu, l1, 2);

    // Epilogue: normalize, write att fp16 [token][h*64+d]
    const float inv0 = 1.0f / l0, inv1 = 1.0f / l1;
    const int b  = bh >> 4;
    const int hh = bh & 15;
    const int r0 = qt * 128 + w * 16 + (lane >> 2);
    const int r1 = r0 + 8;
    const int col0 = hh * HEAD_DIM + ((lane & 3) << 1);
#pragma unroll
    for (int j = 0; j < 8; j++) {
        size_t o0 = (size_t)(b * N_SEQ + r0) * D_MODEL + col0 + 8 * j;
        *(uint32_t*)&g_att_f[o0] = pack_h2(o[j][0] * inv0, o[j][1] * inv0);
        size_t o1 = (size_t)(b * N_SEQ + r1) * D_MODEL + col0 + 8 * j;
        *(uint32_t*)&g_att_f[o1] = pack_h2(o[j][2] * inv1, o[j][3] * inv1);
    }
}

// ---------------------------------------------------------------------------
// Launch
// ---------------------------------------------------------------------------
extern "C" void kernel_launch(void* const* d_in, const int* in_sizes, int n_in,
                              void* d_out, int out_size)
{
    const float* x      = (const float*)d_in[0];
    const float* W_qkv  = (const float*)d_in[1];
    const float* b_qkv  = (const float*)d_in[2];
    const float* W_out  = (const float*)d_in[3];
    const float* b_out  = (const float*)d_in[4];
    float* out = (float*)d_out;

    static __half *xf = nullptr, *wqf, *wof, *atf;
    static bool init_done = false;
    if (!init_done) {
        cudaGetSymbolAddress((void**)&xf,  g_x_f);
        cudaGetSymbolAddress((void**)&wqf, g_wqkv_f);
        cudaGetSymbolAddress((void**)&wof, g_wout_f);
        cudaGetSymbolAddress((void**)&atf, g_att_f);
        cudaFuncSetAttribute(mma_gemm_kernel,
                             cudaFuncAttributeMaxDynamicSharedMemorySize,
                             G_SMEM_B);
        cudaFuncSetAttribute(attn_mma_kernel,
                             cudaFuncAttributeMaxDynamicSharedMemorySize,
                             ATT_SMEM_BYTES);
        init_done = true;
    }

    // 0) fp16 conversions
    {
        int n4 = (TOKENS * D_MODEL) / 4;
        conv_x_kernel<<<n4 / 256, 256>>>(x, xf, n4);
        dim3 blk(32, 8);
        conv_wt_kernel<<<dim3(QKV_COLS / 32, D_MODEL / 32), blk>>>(W_qkv, wqf, QKV_COLS, D_MODEL);
        conv_wt_kernel<<<dim3(D_MODEL / 32, D_MODEL / 32), blk>>>(W_out, wof, D_MODEL, D_MODEL);
    }

    // 1) QKV projection -> fp16 Q/K/Vt
    {
        dim3 grid(QKV_COLS / 128, TOKENS / 128);
        mma_gemm_kernel<<<grid, 256, G_SMEM_B>>>(xf, wqf, b_qkv, nullptr,
                                                 TOKENS, QKV_COLS, D_MODEL, 0);
    }

    // 2) Flash attention (fp16 mma.sync, base-2 softmax, 3-stage cp.async)
    {
        dim3 grid(N_SEQ / 128, BH);
        attn_mma_kernel<<<grid, 256, ATT_SMEM_BYTES>>>();
    }

    // 3) Output projection -> fp32 out
    {
        dim3 grid(D_MODEL / 128, TOKENS / 128);
        mma_gemm_kernel<<<grid, 256, G_SMEM_B>>>(atf, wof, b_out, out,
                                                 TOKENS, D_MODEL, D_MODEL, 1);
    }
}

// round 14
// speedup vs baseline: 3.0705x; 1.0048x over previous
#include <cuda_runtime.h>
#include <cuda_fp16.h>
#include <cstdint>

// Problem constants
#define B_SZ 4
#define N_SEQ 2048
#define D_MODEL 1024
#define N_HEADS 16
#define HEAD_DIM 64
#define BH (B_SZ * N_HEADS)          // 64
#define TOKENS (B_SZ * N_SEQ)        // 8192
#define QKV_COLS (3 * D_MODEL)       // 3072

// ---------------------------------------------------------------------------
// Scratch (module-static device memory; no runtime allocation)
// ---------------------------------------------------------------------------
#define QKV_ELEMS ((size_t)BH * N_SEQ * HEAD_DIM)   // 8388608
__device__ __half g_x_f[(size_t)TOKENS * D_MODEL];
__device__ __half g_wqkv_f[(size_t)QKV_COLS * D_MODEL];   // [n][k]
__device__ __half g_wout_f[(size_t)D_MODEL * D_MODEL];    // [n][k]
__device__ __half g_q_f[QKV_ELEMS];   // [bh][n][dh], pre-scaled by 0.125*log2(e)
__device__ __half g_k_f[QKV_ELEMS];   // [bh][n][dh]
__device__ __half g_vt_f[QKV_ELEMS];  // [bh][dh][n]  (transposed)
__device__ __half g_att_f[(size_t)TOKENS * D_MODEL];  // [token][h*64+dh]

// ---------------------------------------------------------------------------
// Helpers
// ---------------------------------------------------------------------------
__device__ __forceinline__ uint32_t smem_u32(const void* p) {
    uint32_t a;
    asm("{ .reg .u64 t; cvta.to.shared.u64 t, %1; cvt.u32.u64 %0, t; }"
        : "=r"(a) : "l"(p));
    return a;
}

__device__ __forceinline__ uint32_t pack_h2(float x, float y) {
    __half2 h = __floats2half2_rn(x, y);
    return *(uint32_t*)&h;
}

__device__ __forceinline__ float fexp2(float x) {
    float y;
    asm("ex2.approx.f32 %0, %1;" : "=f"(y) : "f"(x));
    return y;
}

__device__ __forceinline__ uint32_t h2exp2(uint32_t x) {
    uint32_t y;
    asm("ex2.approx.f16x2 %0, %1;" : "=r"(y) : "r"(x));
    return y;
}

#define ONES_H2 0x3C003C00u   // half2(1.0, 1.0)

#define LDSM_X4(r0, r1, r2, r3, addr) \
    asm volatile("ldmatrix.sync.aligned.m8n8.x4.shared.b16 {%0,%1,%2,%3}, [%4];" \
                 : "=r"(r0), "=r"(r1), "=r"(r2), "=r"(r3) : "r"(addr))

#define MMA_F16(c, a, b0, b1) \
    asm volatile("mma.sync.aligned.m16n8k16.row.col.f32.f16.f16.f32 " \
                 "{%0,%1,%2,%3}, {%4,%5,%6,%7}, {%8,%9}, {%0,%1,%2,%3};" \
                 : "+f"((c)[0]), "+f"((c)[1]), "+f"((c)[2]), "+f"((c)[3]) \
                 : "r"((a)[0]), "r"((a)[1]), "r"((a)[2]), "r"((a)[3]), \
                   "r"(b0), "r"(b1))

#define CP16(saddr, gptr) \
    asm volatile("cp.async.cg.shared.global [%0], [%1], 16;" \
                 :: "r"(saddr), "l"(gptr) : "memory")
#define CP_COMMIT() asm volatile("cp.async.commit_group;" ::: "memory")
#define CP_WAIT(n)  asm volatile("cp.async.wait_group %0;" :: "n"(n) : "memory")

// Q pre-scale: (1/sqrt(64)) * log2(e), so softmax runs in base-2 domain.
#define Q_SCALE 0.1803368801111244f

// ---------------------------------------------------------------------------
// Conversion kernels (fp32 -> fp16)
// ---------------------------------------------------------------------------
__global__ void conv_x_kernel(const float* __restrict__ x, __half* __restrict__ o, int n4)
{
    int idx = blockIdx.x * 256 + threadIdx.x;
    if (idx >= n4) return;
    float4 v = ((const float4*)x)[idx];
    ((uint2*)o)[idx] = make_uint2(pack_h2(v.x, v.y), pack_h2(v.z, v.w));
}

// W[k][n] fp32 -> Wt[n][k] fp16 (tiled transpose)
__global__ void conv_wt_kernel(const float* __restrict__ W, __half* __restrict__ o,
                               int N, int K)
{
    __shared__ float t[32][33];
    const int tx = threadIdx.x, ty = threadIdx.y;  // block (32,8)
    const int n0 = blockIdx.x * 32, k0 = blockIdx.y * 32;
#pragma unroll
    for (int s = 0; s < 4; s++)
        t[ty + 8 * s][tx] = W[(size_t)(k0 + ty + 8 * s) * N + n0 + tx];
    __syncthreads();
#pragma unroll
    for (int s = 0; s < 4; s++) {
        const int nn = ty + 8 * s, kk = tx;
        o[(size_t)(n0 + nn) * K + k0 + kk] = __float2half_rn(t[kk][nn]);
    }
}

// ---------------------------------------------------------------------------
// Warp-MMA fp16 GEMM, BK=64, 3-stage cp.async ring (one barrier per iter).
// C[M,N] = A[M,K] @ Bt[N,K]^T + bias[N].  BM=BN=128, 256 thr, 8 warps.
// mode 0: QKV epilogue -> fp16 Q/K/Vt; mode 1: fp32 write + bias.
// ---------------------------------------------------------------------------
#define SSTRIDE 72
#define G_ARR_B (128 * SSTRIDE * 2)          // 18432 bytes per array (128x64 fp16)
#define G_STAGE_B (2 * G_ARR_B)              // 36864 per stage (A|B)
#define G_SMEM_B (3 * G_STAGE_B)             // 110592

__global__ void __launch_bounds__(256, 2)
mma_gemm_kernel(const __half* __restrict__ A_g, const __half* __restrict__ B_g,
                const float* __restrict__ bias, float* __restrict__ C,
                int M, int N, int K, int mode)
{
    extern __shared__ __align__(16) char dsm[];
    const uint32_t sb0 = smem_u32(dsm);

    const int tid  = threadIdx.x;
    const int wid  = tid >> 5;
    const int lane = tid & 31;
    const int wr   = wid >> 1;
    const int wc   = wid & 1;

    const int row0 = blockIdx.y * 128;
    const int col0 = blockIdx.x * 128;

    float acc[2][8][4];
#pragma unroll
    for (int i = 0; i < 2; i++)
#pragma unroll
        for (int j = 0; j < 8; j++)
#pragma unroll
            for (int c = 0; c < 4; c++) acc[i][j][c] = 0.f;

    const uint32_t a_row = lane & 15;
    const uint32_t a_kof = (lane >> 4) << 3;
    const uint32_t b_nof = ((lane >> 4) << 3) + (lane & 7);
    const uint32_t b_kof = ((lane >> 3) & 1) << 3;

    // Load coords: 1024 16B chunks per array, 4 per thread.
    // Hoist global base pointers (kills 64-bit IMADs in the issue path).
    uint32_t lso[4];
    const __half* ap[4];
    const __half* bp[4];
#pragma unroll
    for (int i = 0; i < 4; i++) {
        int f = i * 256 + tid;
        int r = f >> 3;
        int c = (f & 7) << 3;
        lso[i] = ((uint32_t)r * SSTRIDE + c) * 2;
        ap[i] = A_g + (size_t)(row0 + r) * K + c;
        bp[i] = B_g + (size_t)(col0 + r) * K + c;
    }

#define G_ISSUE(stage, k0_)                                                     \
    do {                                                                        \
        uint32_t sb = sb0 + (stage) * G_STAGE_B;                                \
        _Pragma("unroll")                                                       \
        for (int i = 0; i < 4; i++) {                                           \
            CP16(sb + lso[i],           ap[i] + (k0_));                         \
            CP16(sb + G_ARR_B + lso[i], bp[i] + (k0_));                         \
        }                                                                       \
        CP_COMMIT();                                                            \
    } while (0)

    const int niter = K / 64;
    G_ISSUE(0, 0);
    G_ISSUE(1, 64);

    for (int it = 0; it < niter; it++) {
        if (it + 1 < niter) { CP_WAIT(1); } else { CP_WAIT(0); }
        __syncthreads();

        const uint32_t sb  = sb0 + (it % 3) * G_STAGE_B;
        const uint32_t a_b = sb;
        const uint32_t b_b = sb + G_ARR_B;

#pragma unroll
        for (int ks = 0; ks < 4; ks++) {
            const uint32_t kk = ks * 16;
            uint32_t ar[2][4];
#pragma unroll
            for (int i = 0; i < 2; i++) {
                uint32_t eoff = ((wr * 32 + i * 16 + a_row) * SSTRIDE + kk + a_kof) * 2;
                LDSM_X4(ar[i][0], ar[i][1], ar[i][2], ar[i][3], a_b + eoff);
            }
#pragma unroll
            for (int jp = 0; jp < 4; jp++) {
                const uint32_t nb = wc * 64 + jp * 16;
                uint32_t eoff = ((nb + b_nof) * SSTRIDE + kk + b_kof) * 2;
                uint32_t br[4];
                LDSM_X4(br[0], br[1], br[2], br[3], b_b + eoff);
#pragma unroll
                for (int i = 0; i < 2; i++) {
                    MMA_F16(acc[i][2 * jp + 0], ar[i], br[0], br[1]);
                    MMA_F16(acc[i][2 * jp + 1], ar[i], br[2], br[3]);
                }
            }
        }
        if (it + 2 < niter) G_ISSUE((it + 2) % 3, (it + 2) * 64);
    }
#undef G_ISSUE

    const int mbase = row0 + wr * 32 + (lane >> 2);
    const int nbase = col0 + wc * 64 + ((lane & 3) << 1);

    if (mode == 0) {
#pragma unroll
        for (int i = 0; i < 2; i++) {
#pragma unroll
            for (int rr = 0; rr < 2; rr++) {
                const int m  = mbase + i * 16 + rr * 8;
                const int bb = m >> 11;
                const int nn = m & 2047;
#pragma unroll
                for (int j = 0; j < 8; j++) {
                    const int jg0 = nbase + j * 8;
                    const int sel = jg0 >> 10;
                    const int hh  = (jg0 >> 6) & 15;
                    const int dh  = jg0 & 63;
                    const int bhd = bb * N_HEADS + hh;
                    float v0 = acc[i][j][rr * 2 + 0] + bias[jg0];
                    float v1 = acc[i][j][rr * 2 + 1] + bias[jg0 + 1];
                    if (sel == 0) { v0 *= Q_SCALE; v1 *= Q_SCALE; }
                    if (sel == 0) {
                        size_t o = ((size_t)bhd * N_SEQ + nn) * HEAD_DIM + dh;
                        *(uint32_t*)&g_q_f[o] = pack_h2(v0, v1);
                    } else if (sel == 1) {
                        size_t o = ((size_t)bhd * N_SEQ + nn) * HEAD_DIM + dh;
                        *(uint32_t*)&g_k_f[o] = pack_h2(v0, v1);
                    } else {
                        size_t o = ((size_t)bhd * HEAD_DIM + dh) * N_SEQ + nn;
                        g_vt_f[o] = __float2half_rn(v0);
                        g_vt_f[o + N_SEQ] = __float2half_rn(v1);
                    }
                }
            }
        }
    } else {
#pragma unroll
        for (int i = 0; i < 2; i++) {
#pragma unroll
            for (int rr = 0; rr < 2; rr++) {
                const int m = mbase + i * 16 + rr * 8;
                float* cp = C + (size_t)m * N;
#pragma unroll
                for (int j = 0; j < 8; j++) {
#pragma unroll
                    for (int c = 0; c < 2; c++) {
                        const int jg = nbase + j * 8 + c;
                        cp[jg] = acc[i][j][rr * 2 + c] + bias[jg];
                    }
                }
            }
        }
    }
}

// ---------------------------------------------------------------------------
// mma.sync fp16 flash attention, 3-stage cp.async KV ring, 2 CTAs/SM.
// Base-2 online softmax; exp via ex2.approx.f16x2 (half the MUFU ops);
// softmax denominator via ones-MMA row-sum (tensor pipe, no shuffles).
// smem: Q [128][72] fp16 + 3 stages x (K|V) [64][72] fp16 = 73728 B.
// ---------------------------------------------------------------------------
#define AQ_STR 72
#define A_Q_ARR_B (128 * AQ_STR * 2)     // 18432
#define A_KV_ARR_B (64 * AQ_STR * 2)     // 9216
#define A_KV_STAGE_B (2 * A_KV_ARR_B)    // 18432
#define A_KV_BASE A_Q_ARR_B              // 18432
#define ATT_SMEM_BYTES (A_KV_BASE + 3 * A_KV_STAGE_B)   // 73728

__global__ void __launch_bounds__(256, 2)
attn_mma_kernel()
{
    extern __shared__ __align__(16) char dsm[];
    const uint32_t sb0  = smem_u32(dsm);
    const uint32_t q_b  = sb0;

    const int tid  = threadIdx.x;
    const int w    = tid >> 5;
    const int lane = tid & 31;
    const int bh   = blockIdx.y;
    const int qt   = blockIdx.x;

    const __half* ksrc = g_k_f + (size_t)bh * N_SEQ * HEAD_DIM;
    const __half* vsrc = g_vt_f + (size_t)bh * HEAD_DIM * N_SEQ;

    const int f0 = tid, f1 = 256 + tid;
    const int kr0 = f0 >> 3, kc0 = (f0 & 7) << 3;
    const int kr1 = f1 >> 3, kc1 = (f1 & 7) << 3;
    const uint32_t kso0 = ((uint32_t)kr0 * AQ_STR + kc0) * 2;
    const uint32_t kso1 = ((uint32_t)kr1 * AQ_STR + kc1) * 2;

#define A_ISSUE(stage, kt_)                                                     \
    do {                                                                        \
        uint32_t sb = sb0 + A_KV_BASE + (stage) * A_KV_STAGE_B;                 \
        CP16(sb + kso0,               ksrc + (size_t)((kt_) * 64 + kr0) * HEAD_DIM + kc0); \
        CP16(sb + kso1,               ksrc + (size_t)((kt_) * 64 + kr1) * HEAD_DIM + kc1); \
        CP16(sb + A_KV_ARR_B + kso0,  vsrc + (size_t)kr0 * N_SEQ + (kt_) * 64 + kc0); \
        CP16(sb + A_KV_ARR_B + kso1,  vsrc + (size_t)kr1 * N_SEQ + (kt_) * 64 + kc1); \
        CP_COMMIT();                                                            \
    } while (0)

    A_ISSUE(0, 0);
    A_ISSUE(1, 1);

    // Load Q tile [128][64] fp16 (plain loads, once)
    const __half* qsrc = g_q_f + ((size_t)bh * N_SEQ + qt * 128) * HEAD_DIM;
#pragma unroll
    for (int i = 0; i < 4; i++) {
        int f  = i * 256 + tid;
        int r  = f >> 3;
        int c8 = (f & 7) << 3;
        uint32_t so = ((uint32_t)r * AQ_STR + c8) * 2;
        *(uint4*)(dsm + so) = *(const uint4*)(qsrc + r * HEAD_DIM + c8);
    }

    const uint32_t a_row = lane & 15;
    const uint32_t a_kof = (lane >> 4) << 3;
    const uint32_t b_nof = ((lane >> 4) << 3) + (lane & 7);
    const uint32_t b_kof = ((lane >> 3) & 1) << 3;

    float m0 = -1e30f, m1 = -1e30f, l0 = 0.f, l1 = 0.f;
    float o[8][4];
#pragma unroll
    for (int j = 0; j < 8; j++)
#pragma unroll
        for (int c = 0; c < 4; c++) o[j][c] = 0.f;

    const int nkt = N_SEQ / 64;
    for (int kt = 0; kt < nkt; kt++) {
        if (kt + 1 < nkt) { CP_WAIT(1); } else { CP_WAIT(0); }
        __syncthreads();

        const uint32_t sb  = sb0 + A_KV_BASE + (kt % 3) * A_KV_STAGE_B;
        const uint32_t k_b = sb;
        const uint32_t v_b = sb + A_KV_ARR_B;

        // S = Q @ K^T (base-2 scale pre-folded into Q)
        float s[8][4];
#pragma unroll
        for (int j = 0; j < 8; j++)
#pragma unroll
            for (int c = 0; c < 4; c++) s[j][c] = 0.f;

#pragma unroll
        for (int t = 0; t < 4; t++) {
            uint32_t q4[4];
            {
                uint32_t eoff = ((w * 16 + a_row) * AQ_STR + t * 16 + a_kof) * 2;
                LDSM_X4(q4[0], q4[1], q4[2], q4[3], q_b + eoff);
            }
#pragma unroll
            for (int g = 0; g < 4; g++) {
                uint32_t eoff = ((g * 16 + b_nof) * AQ_STR + t * 16 + b_kof) * 2;
                uint32_t k4[4];
                LDSM_X4(k4[0], k4[1], k4[2], k4[3], k_b + eoff);
                MMA_F16(s[2 * g + 0], q4, k4[0], k4[1]);
                MMA_F16(s[2 * g + 1], q4, k4[2], k4[3]);
            }
        }

        // Row max (fp32) shared by 4-lane groups
        float mx0 = -1e30f, mx1 = -1e30f;
#pragma unroll
        for (int j = 0; j < 8; j++) {
            mx0 = fmaxf(mx0, fmaxf(s[j][0], s[j][1]));
            mx1 = fmaxf(mx1, fmaxf(s[j][2], s[j][3]));
        }
        mx0 = fmaxf(mx0, __shfl_xor_sync(0xffffffffu, mx0, 1));
        mx0 = fmaxf(mx0, __shfl_xor_sync(0xffffffffu, mx0, 2));
        mx1 = fmaxf(mx1, __shfl_xor_sync(0xffffffffu, mx1, 1));
        mx1 = fmaxf(mx1, __shfl_xor_sync(0xffffffffu, mx1, 2));
        float mn0 = fmaxf(m0, mx0), mn1 = fmaxf(m1, mx1);
        float sc0 = fexp2(m0 - mn0), sc1 = fexp2(m1 - mn1);
        m0 = mn0; m1 = mn1;

        // Rescale O before accumulating this tile's PV
#pragma unroll
        for (int j = 0; j < 8; j++) {
            o[j][0] *= sc0; o[j][1] *= sc0;
            o[j][2] *= sc1; o[j][3] *= sc1;
        }

        // P = exp2(S - m) computed as half2 fragments (ex2.approx.f16x2).
        // O += P @ V; denominator via ones-MMA row sum (complete across lanes).
        float lacc[4] = {0.f, 0.f, 0.f, 0.f};
#pragma unroll
        for (int t = 0; t < 4; t++) {
            uint32_t p4[4];
            p4[0] = h2exp2(pack_h2(s[2 * t][0] - m0,     s[2 * t][1] - m0));
            p4[1] = h2exp2(pack_h2(s[2 * t][2] - m1,     s[2 * t][3] - m1));
            p4[2] = h2exp2(pack_h2(s[2 * t + 1][0] - m0, s[2 * t + 1][1] - m0));
            p4[3] = h2exp2(pack_h2(s[2 * t + 1][2] - m1, s[2 * t + 1][3] - m1));
            MMA_F16(lacc, p4, ONES_H2, ONES_H2);
#pragma unroll
            for (int g = 0; g < 4; g++) {
                uint32_t eoff = ((g * 16 + b_nof) * AQ_STR + t * 16 + b_kof) * 2;
                uint32_t v4[4];
                LDSM_X4(v4[0], v4[1], v4[2], v4[3], v_b + eoff);
                MMA_F16(o[2 * g + 0], p4, v4[0], v4[1]);
                MMA_F16(o[2 * g + 1], p4, v4[2], v4[3]);
            }
        }
        l0 = l0 * sc0 + lacc[0];
        l1 = l1 * sc1 + lacc[2];

        if (kt + 2 < nkt) A_ISSUE((kt + 2) % 3, kt + 2);
    }
#undef A_ISSUE

    // Epilogue: normalize, write att fp16 [token][h*64+d]
    const float inv0 = 1.0f / l0, inv1 = 1.0f / l1;
    const int b  = bh >> 4;
    const int hh = bh & 15;
    const int r0 = qt * 128 + w * 16 + (lane >> 2);
    const int r1 = r0 + 8;
    const int col0 = hh * HEAD_DIM + ((lane & 3) << 1);
#pragma unroll
    for (int j = 0; j < 8; j++) {
        size_t o0 = (size_t)(b * N_SEQ + r0) * D_MODEL + col0 + 8 * j;
        *(uint32_t*)&g_att_f[o0] = pack_h2(o[j][0] * inv0, o[j][1] * inv0);
        size_t o1 = (size_t)(b * N_SEQ + r1) * D_MODEL + col0 + 8 * j;
        *(uint32_t*)&g_att_f[o1] = pack_h2(o[j][2] * inv1, o[j][3] * inv1);
    }
}

// ---------------------------------------------------------------------------
// Launch
// ---------------------------------------------------------------------------
extern "C" void kernel_launch(void* const* d_in, const int* in_sizes, int n_in,
                              void* d_out, int out_size)
{
    const float* x      = (const float*)d_in[0];
    const float* W_qkv  = (const float*)d_in[1];
    const float* b_qkv  = (const float*)d_in[2];
    const float* W_out  = (const float*)d_in[3];
    const float* b_out  = (const float*)d_in[4];
    float* out = (float*)d_out;

    static __half *xf = nullptr, *wqf, *wof, *atf;
    static bool init_done = false;
    if (!init_done) {
        cudaGetSymbolAddress((void**)&xf,  g_x_f);
        cudaGetSymbolAddress((void**)&wqf, g_wqkv_f);
        cudaGetSymbolAddress((void**)&wof, g_wout_f);
        cudaGetSymbolAddress((void**)&atf, g_att_f);
        cudaFuncSetAttribute(mma_gemm_kernel,
                             cudaFuncAttributeMaxDynamicSharedMemorySize,
                             G_SMEM_B);
        cudaFuncSetAttribute(attn_mma_kernel,
                             cudaFuncAttributeMaxDynamicSharedMemorySize,
                             ATT_SMEM_BYTES);
        init_done = true;
    }

    // 0) fp16 conversions
    {
        int n4 = (TOKENS * D_MODEL) / 4;
        conv_x_kernel<<<n4 / 256, 256>>>(x, xf, n4);
        dim3 blk(32, 8);
        conv_wt_kernel<<<dim3(QKV_COLS / 32, D_MODEL / 32), blk>>>(W_qkv, wqf, QKV_COLS, D_MODEL);
        conv_wt_kernel<<<dim3(D_MODEL / 32, D_MODEL / 32), blk>>>(W_out, wof, D_MODEL, D_MODEL);
    }

    // 1) QKV projection -> fp16 Q/K/Vt
    {
        dim3 grid(QKV_COLS / 128, TOKENS / 128);
        mma_gemm_kernel<<<grid, 256, G_SMEM_B>>>(xf, wqf, b_qkv, nullptr,
                                                 TOKENS, QKV_COLS, D_MODEL, 0);
    }

    // 2) Flash attention (fp16 mma.sync, f16x2 exp, ones-MMA denominator)
    {
        dim3 grid(N_SEQ / 128, BH);
        attn_mma_kernel<<<grid, 256, ATT_SMEM_BYTES>>>();
    }

    // 3) Output projection -> fp32 out
    {
        dim3 grid(D_MODEL / 128, TOKENS / 128);
        mma_gemm_kernel<<<grid, 256, G_SMEM_B>>>(atf, wof, b_out, out,
                                                 TOKENS, D_MODEL, D_MODEL, 1);
    }
}